// round 6
// baseline (speedup 1.0000x reference)
#include <cuda_runtime.h>
#include <math_constants.h>

// Bidirectional Chamfer distance, B=4, N=M=4096, D=3, fp32.
// dist = |q|^2 + |t|^2 - 2 q.t
// Single persistent launch, 128 co-resident blocks x 1024 threads:
//  phase 1: block = 2048 queries x 512-target tile, f32x2 FMA inner loop,
//           QPT=2, 8 warps/SMSP for LDS-latency hiding, partials plain-stored.
//  phase 2: device-wide spin barrier, cooperative min-across-tiles + slice sum.
//  phase 3: last block sums 128 block sums in fixed order (deterministic).

#define BATCH   4
#define NPTS    4096
#define THREADS 1024
#define QPT     2
#define QBLK    (THREADS * QPT)      // 2048 queries per block
#define NQBLK   (NPTS / QBLK)        // 2
#define NTTILE  8                    // target tiles
#define TT      (NPTS / NTTILE)      // 512 targets per tile
#define TTP     (TT / 2)             // 256 target pairs
#define NDIRB   (2 * BATCH)          // 8
#define NBLK    (NQBLK * NTTILE * NDIRB)  // 128 blocks
#define ENT     (NDIRB * NPTS)       // 32768 final entries
#define SLICE   (ENT / NBLK)         // 256 entries per block in phase 2

__device__ float        g_part[NTTILE * ENT];  // [tile][dirb*NPTS+q]
__device__ float        g_bsum[NBLK];
__device__ unsigned int g_count0;              // zero-init; reset by last block
__device__ unsigned int g_count1;

__global__ __launch_bounds__(THREADS, 1)
void chamfer_kernel(const float* __restrict__ src,
                    const float* __restrict__ tgt,
                    float* __restrict__ out) {
    // s_xy[p] = (-2x0,-2x1,-2y0,-2y1), s_zw[p] = (-2z0,-2z1,|t0|^2,|t1|^2)
    __shared__ float4 s_xy[TTP];
    __shared__ float4 s_zw[TTP];
    __shared__ float  s_wsum[THREADS / 32];

    const int tile = blockIdx.y;
    const int bz   = blockIdx.z;     // 0..7 = b*2 + dir
    const int b    = bz >> 1;
    const int dir  = bz & 1;

    const float* __restrict__ qbase = (dir ? tgt : src) + (size_t)b * NPTS * 3;
    const float* __restrict__ tbase = (dir ? src : tgt) + (size_t)b * NPTS * 3;

    // ---- phase 1a: preprocess this target tile (512 pts) into paired layout
    {
        const float4* __restrict__ t4 =
            reinterpret_cast<const float4*>(tbase + (size_t)tile * TT * 3);
        if (threadIdx.x < TT / 4) {
            int g = threadIdx.x;
            float4 A = t4[3 * g + 0];
            float4 Bv = t4[3 * g + 1];
            float4 C = t4[3 * g + 2];
            // pts: (A.x,A.y,A.z)(A.w,B.x,B.y)(B.z,B.w,C.x)(C.y,C.z,C.w)
            s_xy[2 * g + 0] = make_float4(-2.0f * A.x, -2.0f * A.w,
                                          -2.0f * A.y, -2.0f * Bv.x);
            s_zw[2 * g + 0] = make_float4(-2.0f * A.z, -2.0f * Bv.y,
                fmaf(A.x, A.x, fmaf(A.y, A.y, A.z * A.z)),
                fmaf(A.w, A.w, fmaf(Bv.x, Bv.x, Bv.y * Bv.y)));
            s_xy[2 * g + 1] = make_float4(-2.0f * Bv.z, -2.0f * C.y,
                                          -2.0f * Bv.w, -2.0f * C.z);
            s_zw[2 * g + 1] = make_float4(-2.0f * C.x, -2.0f * C.w,
                fmaf(Bv.z, Bv.z, fmaf(Bv.w, Bv.w, C.x * C.x)),
                fmaf(C.y, C.y, fmaf(C.z, C.z, C.w * C.w)));
        }
    }
    __syncthreads();

    // ---- phase 1b: 2 queries/thread, min over the tile
    const int q0 = blockIdx.x * QBLK + threadIdx.x;
    unsigned long long qx2[QPT], qy2[QPT], qz2[QPT];
    float q2[QPT], mn[QPT];
#pragma unroll
    for (int j = 0; j < QPT; j++) {
        int q = q0 + j * THREADS;
        float x = qbase[q * 3 + 0];
        float y = qbase[q * 3 + 1];
        float z = qbase[q * 3 + 2];
        asm("mov.b64 %0, {%1, %1};" : "=l"(qx2[j]) : "f"(x));
        asm("mov.b64 %0, {%1, %1};" : "=l"(qy2[j]) : "f"(y));
        asm("mov.b64 %0, {%1, %1};" : "=l"(qz2[j]) : "f"(z));
        q2[j] = fmaf(x, x, fmaf(y, y, z * z));
        mn[j] = CUDART_INF_F;
    }

    const ulonglong2* __restrict__ pXY = reinterpret_cast<const ulonglong2*>(s_xy);
    const ulonglong2* __restrict__ pZW = reinterpret_cast<const ulonglong2*>(s_zw);

    // per warp-iter: 2 LDS.128 (broadcast) + 6 FFMA2 (fma) + 4 FMNMX (alu)
    //   = 12 issues, 12 fma-pipe cycles -> simultaneously issue/fma saturable
#pragma unroll 2
    for (int p = 0; p < TTP; p++) {
        ulonglong2 xy = pXY[p];   // (x0,x1),(y0,y1)
        ulonglong2 zw = pZW[p];   // (z0,z1),(w0,w1)
#pragma unroll
        for (int j = 0; j < QPT; j++) {
            float s0, s1;
            asm("{\n\t"
                ".reg .b64 d;\n\t"
                "fma.rn.f32x2 d, %2, %3, %4;\n\t"
                "fma.rn.f32x2 d, %5, %6, d;\n\t"
                "fma.rn.f32x2 d, %7, %8, d;\n\t"
                "mov.b64 {%0, %1}, d;\n\t"
                "}"
                : "=f"(s0), "=f"(s1)
                : "l"(zw.x), "l"(qz2[j]), "l"(zw.y),
                  "l"(xy.y), "l"(qy2[j]),
                  "l"(xy.x), "l"(qx2[j]));
            mn[j] = fminf(mn[j], fminf(s0, s1));
        }
    }

    // ---- phase 1c: store partial mins (|q|^2 folded in)
    float* part = g_part + (size_t)tile * ENT + (size_t)bz * NPTS;
#pragma unroll
    for (int j = 0; j < QPT; j++)
        part[q0 + j * THREADS] = mn[j] + q2[j];

    // ---- device-wide barrier (all 128 blocks co-resident: grid <= #SMs)
    __shared__ unsigned int s_go;
    __threadfence();
    __syncthreads();
    if (threadIdx.x == 0) {
        atomicAdd(&g_count0, 1u);
        while (atomicAdd(&g_count0, 0u) < NBLK) { __nanosleep(64); }
        s_go = 1u;
    }
    __syncthreads();
    __threadfence();
    (void)s_go;

    // ---- phase 2: min across tiles + slice sum (fixed order)
    const int k = (bz * NTTILE + tile) * NQBLK + blockIdx.x;  // flat block id
    float local = 0.0f;
    if (threadIdx.x < SLICE) {
        int e = k * SLICE + threadIdx.x;
        float v = g_part[e];
#pragma unroll
        for (int t = 1; t < NTTILE; t++)
            v = fminf(v, g_part[t * ENT + e]);
        local = v;
    }
#pragma unroll
    for (int off = 16; off > 0; off >>= 1)
        local += __shfl_down_sync(0xFFFFFFFFu, local, off);
    if ((threadIdx.x & 31) == 0) s_wsum[threadIdx.x >> 5] = local;
    __syncthreads();

    if (threadIdx.x == 0) {
        float bs = 0.0f;
#pragma unroll
        for (int w = 0; w < THREADS / 32; w++) bs += s_wsum[w];
        g_bsum[k] = bs;
        __threadfence();
        unsigned int prev = atomicAdd(&g_count1, 1u);
        // ---- phase 3: last block finalizes (deterministic fixed order)
        if (prev == NBLK - 1) {
            __threadfence();
            float tot = 0.0f;
            for (int i = 0; i < NBLK; i++) tot += g_bsum[i];
            out[0] = tot / (float)(BATCH * NPTS);
            g_count0 = 0;
            g_count1 = 0;
        }
    }
}

extern "C" void kernel_launch(void* const* d_in, const int* in_sizes, int n_in,
                              void* d_out, int out_size) {
    const float* src = (const float*)d_in[0];  // (B, N, 3)
    const float* tgt = (const float*)d_in[1];  // (B, M, 3)
    float* out = (float*)d_out;

    dim3 grid(NQBLK, NTTILE, NDIRB);  // 2 x 8 x 8 = 128 blocks, one wave
    chamfer_kernel<<<grid, THREADS>>>(src, tgt, out);
}

// round 7
// speedup vs baseline: 1.2100x; 1.2100x over previous
#include <cuda_runtime.h>
#include <math_constants.h>

// Bidirectional Chamfer distance, B=4, N=M=4096, D=3, fp32.
// dist = |q|^2 + |t|^2 - 2 q.t
// K1: 1024 small blocks (512 queries x 256-target tile), f32x2 FMA loop,
//     partial mins plain-stored. 1024 blocks @ occ4 -> ~1.4% wave imbalance,
//     all 148 SMs busy.
// K2: 32768 threads, min across 16 tiles + deterministic fixed-order sum with
//     last-block finalize. Two launches total.

#define BATCH   4
#define NPTS    4096
#define THREADS 256
#define QPT     2
#define QBLK    (THREADS * QPT)      // 512 queries per block
#define NQBLK   (NPTS / QBLK)        // 8
#define NTTILE  16                   // target tiles
#define TT      (NPTS / NTTILE)      // 256 targets per tile
#define TTP     (TT / 2)             // 128 target pairs
#define NDIRB   (2 * BATCH)          // 8
#define ENT     (NDIRB * NPTS)       // 32768 final entries

#define R_THREADS 512
#define R_NBLK    (ENT / R_THREADS)  // 64 reduce blocks

__device__ float        g_part[NTTILE * ENT];  // [tile][dirb*NPTS+q]
__device__ float        g_bsum[R_NBLK];
__device__ unsigned int g_count;               // zero-init; reset by last block

__global__ __launch_bounds__(THREADS)
void chamfer_min_kernel(const float* __restrict__ src,
                        const float* __restrict__ tgt) {
    // s_xy[p] = (-2x0,-2x1,-2y0,-2y1), s_zw[p] = (-2z0,-2z1,|t0|^2,|t1|^2)
    __shared__ float4 s_xy[TTP];
    __shared__ float4 s_zw[TTP];

    const int tile = blockIdx.y;
    const int bz   = blockIdx.z;     // 0..7 = b*2 + dir
    const int b    = bz >> 1;
    const int dir  = bz & 1;

    const float* __restrict__ qbase = (dir ? tgt : src) + (size_t)b * NPTS * 3;
    const float* __restrict__ tbase = (dir ? src : tgt) + (size_t)b * NPTS * 3;

    // ---- preprocess this 256-target tile into paired f32x2 layout
    {
        const float4* __restrict__ t4 =
            reinterpret_cast<const float4*>(tbase + (size_t)tile * TT * 3);
        if (threadIdx.x < TT / 4) {
            int g = threadIdx.x;
            float4 A = t4[3 * g + 0];
            float4 Bv = t4[3 * g + 1];
            float4 C = t4[3 * g + 2];
            // pts: (A.x,A.y,A.z)(A.w,B.x,B.y)(B.z,B.w,C.x)(C.y,C.z,C.w)
            s_xy[2 * g + 0] = make_float4(-2.0f * A.x, -2.0f * A.w,
                                          -2.0f * A.y, -2.0f * Bv.x);
            s_zw[2 * g + 0] = make_float4(-2.0f * A.z, -2.0f * Bv.y,
                fmaf(A.x, A.x, fmaf(A.y, A.y, A.z * A.z)),
                fmaf(A.w, A.w, fmaf(Bv.x, Bv.x, Bv.y * Bv.y)));
            s_xy[2 * g + 1] = make_float4(-2.0f * Bv.z, -2.0f * C.y,
                                          -2.0f * Bv.w, -2.0f * C.z);
            s_zw[2 * g + 1] = make_float4(-2.0f * C.x, -2.0f * C.w,
                fmaf(Bv.z, Bv.z, fmaf(Bv.w, Bv.w, C.x * C.x)),
                fmaf(C.y, C.y, fmaf(C.z, C.z, C.w * C.w)));
        }
    }
    __syncthreads();

    // ---- 2 queries/thread, min over the tile
    const int q0 = blockIdx.x * QBLK + threadIdx.x;
    unsigned long long qx2[QPT], qy2[QPT], qz2[QPT];
    float q2[QPT], mn[QPT];
#pragma unroll
    for (int j = 0; j < QPT; j++) {
        int q = q0 + j * THREADS;
        float x = qbase[q * 3 + 0];
        float y = qbase[q * 3 + 1];
        float z = qbase[q * 3 + 2];
        asm("mov.b64 %0, {%1, %1};" : "=l"(qx2[j]) : "f"(x));
        asm("mov.b64 %0, {%1, %1};" : "=l"(qy2[j]) : "f"(y));
        asm("mov.b64 %0, {%1, %1};" : "=l"(qz2[j]) : "f"(z));
        q2[j] = fmaf(x, x, fmaf(y, y, z * z));
        mn[j] = CUDART_INF_F;
    }

    const ulonglong2* __restrict__ pXY = reinterpret_cast<const ulonglong2*>(s_xy);
    const ulonglong2* __restrict__ pZW = reinterpret_cast<const ulonglong2*>(s_zw);

    // per warp-iter: 2 LDS.128 (broadcast) + 6 FFMA2 (fma pipe, rt4)
    //                + 4 FMNMX (alu pipe)
#pragma unroll 4
    for (int p = 0; p < TTP; p++) {
        ulonglong2 xy = pXY[p];   // (x0,x1),(y0,y1)
        ulonglong2 zw = pZW[p];   // (z0,z1),(w0,w1)
#pragma unroll
        for (int j = 0; j < QPT; j++) {
            float s0, s1;
            asm("{\n\t"
                ".reg .b64 d;\n\t"
                "fma.rn.f32x2 d, %2, %3, %4;\n\t"
                "fma.rn.f32x2 d, %5, %6, d;\n\t"
                "fma.rn.f32x2 d, %7, %8, d;\n\t"
                "mov.b64 {%0, %1}, d;\n\t"
                "}"
                : "=f"(s0), "=f"(s1)
                : "l"(zw.x), "l"(qz2[j]), "l"(zw.y),
                  "l"(xy.y), "l"(qy2[j]),
                  "l"(xy.x), "l"(qx2[j]));
            mn[j] = fminf(mn[j], fminf(s0, s1));
        }
    }

    // ---- store partial mins (|q|^2 folded in)
    float* part = g_part + (size_t)tile * ENT + (size_t)bz * NPTS;
#pragma unroll
    for (int j = 0; j < QPT; j++)
        part[q0 + j * THREADS] = mn[j] + q2[j];
}

// K2: entry e -> min over 16 tiles; block sum; last block fixed-order finalize.
__global__ __launch_bounds__(R_THREADS)
void chamfer_reduce_kernel(float* __restrict__ out) {
    __shared__ float s_wsum[R_THREADS / 32];

    const int e = blockIdx.x * R_THREADS + threadIdx.x;  // 0..32767
    float v = g_part[e];
#pragma unroll
    for (int t = 1; t < NTTILE; t++)
        v = fminf(v, g_part[t * ENT + e]);

#pragma unroll
    for (int off = 16; off > 0; off >>= 1)
        v += __shfl_down_sync(0xFFFFFFFFu, v, off);
    if ((threadIdx.x & 31) == 0) s_wsum[threadIdx.x >> 5] = v;
    __syncthreads();

    if (threadIdx.x == 0) {
        float bs = 0.0f;
#pragma unroll
        for (int w = 0; w < R_THREADS / 32; w++) bs += s_wsum[w];
        g_bsum[blockIdx.x] = bs;
        __threadfence();
        unsigned int prev = atomicAdd(&g_count, 1u);
        if (prev == R_NBLK - 1) {       // last block finalizes, fixed order
            __threadfence();
            float tot = 0.0f;
            for (int i = 0; i < R_NBLK; i++) tot += g_bsum[i];
            out[0] = tot / (float)(BATCH * NPTS);
            g_count = 0;                // reset for next graph replay
        }
    }
}

extern "C" void kernel_launch(void* const* d_in, const int* in_sizes, int n_in,
                              void* d_out, int out_size) {
    const float* src = (const float*)d_in[0];  // (B, N, 3)
    const float* tgt = (const float*)d_in[1];  // (B, M, 3)
    float* out = (float*)d_out;

    dim3 grid(NQBLK, NTTILE, NDIRB);  // 8 x 16 x 8 = 1024 blocks
    chamfer_min_kernel<<<grid, THREADS>>>(src, tgt);

    chamfer_reduce_kernel<<<R_NBLK, R_THREADS>>>(out);
}